// round 15
// baseline (speedup 1.0000x reference)
#include <cuda_runtime.h>
#include <cstdint>

// Problem constants
#define NN    2048          // meta nodes
#define MDIM  64            // subgraph nodes
#define DDIM  64            // channels
#define FDIM  4096          // MDIM*DDIM
#define OUTD  64
#define LN_EPS 1e-5f

// ------------------------- scratch (device globals; no allocation) ----------
__device__ float g_Af[NN * NN];     // A (row-major)
__device__ float g_AT[NN * NN];     // A^T
__device__ float g_A2[NN * NN];     // (A^2)^T
__device__ float g_A3[NN * NN];     // (A^3)^T
__device__ float g_X [NN * FDIM];
__device__ float g_B1[NN * FDIM];
__device__ float g_B2[NN * FDIM];
__device__ float g_B3[NN * FDIM];
__device__ float g_Sn[MDIM * MDIM];

// ------------- cast + transpose-cast in one pass: Af and AT ------------------
__global__ void cast_both(const int* __restrict__ a, float* __restrict__ Af,
                          float* __restrict__ AT) {
    __shared__ float tile[32][33];
    int bx = blockIdx.x * 32, by = blockIdx.y * 32;
    int tx = threadIdx.x, ty = threadIdx.y;            // 32x8
    #pragma unroll
    for (int j = 0; j < 32; j += 8) {
        float v = (float)a[(long)(by + ty + j) * NN + bx + tx];
        Af[(long)(by + ty + j) * NN + bx + tx] = v;
        tile[ty + j][tx] = v;
    }
    __syncthreads();
    #pragma unroll
    for (int j = 0; j < 32; j += 8)
        AT[(long)(bx + ty + j) * NN + by + tx] = tile[tx][ty + j];
}

// ------------------------- Sn = D^-1/2 (S+I) D^-1/2 (256 threads) -----------
__global__ void compute_sn(const int* __restrict__ sub_adj, float* __restrict__ Sn) {
    __shared__ float part[MDIM][4];
    __shared__ float dinv[MDIM];
    const int t = threadIdx.x;           // 256
    const int u = t >> 2, q = t & 3;
    float s = 0.0f;
    #pragma unroll
    for (int v = 0; v < 16; v++) s += (float)sub_adj[u * MDIM + q * 16 + v];
    part[u][q] = s;
    __syncthreads();
    if (q == 0)
        dinv[u] = rsqrtf(1.0f + part[u][0] + part[u][1] + part[u][2] + part[u][3]);
    __syncthreads();
    #pragma unroll
    for (int j = 0; j < 16; j++) {
        int idx = t + j * 256;           // 0..4095
        int uu = idx >> 6, vv = idx & 63;
        float a = (float)sub_adj[idx] + (uu == vv ? 1.0f : 0.0f);
        Sn[idx] = dinv[uu] * a * dinv[vv];
    }
}

// ------------------------- mma / cp.async / f32x2 helpers --------------------
__device__ __forceinline__ void mma_tf32(float c[4], const uint32_t a[4],
                                         const uint32_t b[2]) {
    asm volatile(
        "mma.sync.aligned.m16n8k8.row.col.f32.tf32.tf32.f32 "
        "{%0,%1,%2,%3}, {%4,%5,%6,%7}, {%8,%9}, {%0,%1,%2,%3};\n"
        : "+f"(c[0]), "+f"(c[1]), "+f"(c[2]), "+f"(c[3])
        : "r"(a[0]), "r"(a[1]), "r"(a[2]), "r"(a[3]), "r"(b[0]), "r"(b[1]));
}

__device__ __forceinline__ void cp16(float* smem, const float* gmem) {
    uint32_t s = (uint32_t)__cvta_generic_to_shared(smem);
    asm volatile("cp.async.cg.shared.global [%0], [%1], 16;\n" :: "r"(s), "l"(gmem));
}
__device__ __forceinline__ void cp_commit() {
    asm volatile("cp.async.commit_group;\n");
}
template<int W> __device__ __forceinline__ void cp_wait() {
    asm volatile("cp.async.wait_group %0;\n" :: "n"(W));
}

__device__ __forceinline__ unsigned long long pack2(float x) {
    unsigned long long r;
    asm("mov.b64 %0, {%1, %1};" : "=l"(r) : "f"(x));
    return r;
}
__device__ __forceinline__ unsigned long long pack2f(float lo, float hi) {
    unsigned long long r;
    asm("mov.b64 %0, {%1, %2};" : "=l"(r) : "f"(lo), "f"(hi));
    return r;
}
__device__ __forceinline__ void fma2(unsigned long long& d, unsigned long long a,
                                     unsigned long long b) {
    asm("fma.rn.f32x2 %0, %1, %2, %0;" : "+l"(d) : "l"(a), "l"(b));
}
__device__ __forceinline__ float2 unpack2(unsigned long long v) {
    float2 f;
    asm("mov.b64 {%0, %1}, %2;" : "=f"(f.x), "=f"(f.y) : "l"(v));
    return f;
}

// ---------------- tensor-core GEMM: C(MxN) = (AT)^T (MxK) * B(KxN) ----------
// CTA 256x128x32, 256 threads, warp tile 64x64, 4 stages.
// PDL: A-operand is always >=2 kernels old, so A-prologue is staged BEFORE
// cudaGridDependencySynchronize(); B-operand (immediate producer) after.
// Commit groups: group0 = {A stages 0..2, B stage 0}, group1 = B1, group2 = B2
// -> cp_wait<2> at iter i still guarantees stage i complete.
#define TBM 256
#define TBN 128
#define TBK 32
#define STAGES 4
#define ASPAD 264
#define BSPAD 136
#define GEMM_SMEM (STAGES * TBK * (ASPAD + BSPAD) * 4)   // 204800 bytes

__global__ __launch_bounds__(256, 1)
void gemm_tt(const float* __restrict__ AT, const float* __restrict__ B,
             float* __restrict__ C, int M, int N, int K) {
    extern __shared__ float sm[];
    float (*As)[TBK][ASPAD] = (float (*)[TBK][ASPAD])sm;
    float (*Bs)[TBK][BSPAD] = (float (*)[TBK][BSPAD])(sm + STAGES * TBK * ASPAD);

    const int t  = threadIdx.x;               // 0..255
    const long bm = (long)blockIdx.y * TBM;
    const long bn = (long)blockIdx.x * TBN;
    const int lane = t & 31;
    const int g  = lane >> 2;                 // 0..7
    const int tg = lane & 3;                  // 0..3
    const int w  = t >> 5;                    // 0..7
    const int wm = (w >> 1) * 64;             // 0,64,128,192
    const int wn = (w & 1) * 64;              // 0 or 64

    const int akk = t >> 3;
    const int ac0 = (t & 7) * 4;
    const int asw = ((akk >> 4) & 1) << 4;
    const float* Ag = AT + (long)akk * M + bm;
    const int bkk = t >> 5;
    const int bn4 = (t & 31) * 4;
    const float* Bg = B + (long)bkk * N + bn + bn4;

    float c[4][8][4];
    #pragma unroll
    for (int im = 0; im < 4; im++)
        #pragma unroll
        for (int in = 0; in < 8; in++) {
            c[im][in][0] = 0.f; c[im][in][1] = 0.f;
            c[im][in][2] = 0.f; c[im][in][3] = 0.f;
        }

    const int ktiles = K / TBK;

    // A prologue (safe pre-sync: operand >=2 kernels old), no commits
    #pragma unroll
    for (int s = 0; s < STAGES - 1; s++) {
        const long k0 = (long)s * TBK;
        #pragma unroll
        for (int j = 0; j < 8; j++)
            cp16(&As[s][akk][(ac0 + 32 * j) ^ asw], Ag + k0 * M + ac0 + 32 * j);
    }
    cudaTriggerProgrammaticLaunchCompletion();
    cudaGridDependencySynchronize();
    // B prologue (producer data) + commits
    #pragma unroll
    for (int s = 0; s < STAGES - 1; s++) {
        const long k0 = (long)s * TBK;
        #pragma unroll
        for (int j = 0; j < 4; j++)
            cp16(&Bs[s][bkk + 8 * j][bn4], Bg + (k0 + 8 * j) * N);
        cp_commit();
    }

    for (int i = 0; i < ktiles; i++) {
        if (i + STAGES - 1 < ktiles) cp_wait<STAGES - 2>(); else cp_wait<0>();
        __syncthreads();

        const int nx = i + STAGES - 1;
        if (nx < ktiles) {
            const int st = nx & (STAGES - 1);
            const long k0 = (long)nx * TBK;
            #pragma unroll
            for (int j = 0; j < 8; j++)
                cp16(&As[st][akk][(ac0 + 32 * j) ^ asw], Ag + k0 * M + ac0 + 32 * j);
            #pragma unroll
            for (int j = 0; j < 4; j++)
                cp16(&Bs[st][bkk + 8 * j][bn4], Bg + (k0 + 8 * j) * N);
            cp_commit();
        }

        const int cur = i & (STAGES - 1);
        #pragma unroll
        for (int ks = 0; ks < 4; ks++) {
            const int kr = ks * 8;
            const int sw = (ks >> 1) << 4;
            uint32_t af[4][4], bf[8][2];
            #pragma unroll
            for (int im = 0; im < 4; im++) {
                const int m0 = (wm + im * 16 + g) ^ sw;
                const int m8 = (wm + im * 16 + g + 8) ^ sw;
                af[im][0] = __float_as_uint(As[cur][kr + tg    ][m0]);
                af[im][1] = __float_as_uint(As[cur][kr + tg    ][m8]);
                af[im][2] = __float_as_uint(As[cur][kr + tg + 4][m0]);
                af[im][3] = __float_as_uint(As[cur][kr + tg + 4][m8]);
            }
            #pragma unroll
            for (int in = 0; in < 8; in++) {
                const int nb = wn + in * 8 + g;
                bf[in][0] = __float_as_uint(Bs[cur][kr + tg    ][nb]);
                bf[in][1] = __float_as_uint(Bs[cur][kr + tg + 4][nb]);
            }
            #pragma unroll
            for (int im = 0; im < 4; im++)
                #pragma unroll
                for (int in = 0; in < 8; in++)
                    mma_tf32(c[im][in], af[im], bf[in]);
        }
    }

    #pragma unroll
    for (int im = 0; im < 4; im++) {
        const long row = bm + wm + im * 16 + g;
        #pragma unroll
        for (int in = 0; in < 8; in++) {
            const int col = bn + wn + in * 8 + 2 * tg;
            float* Cp = C + row * N + col;
            *(float2*)Cp           = make_float2(c[im][in][0], c[im][in][1]);
            *(float2*)(Cp + 8 * N) = make_float2(c[im][in][2], c[im][in][3]);
        }
    }
}

// ===== wsum_ln: T = sum_i Xi @ Wi (tensor tf32), then per-n Sn@T + b, LN, ReLU
// CTA = 256 rows = 4 complete n's. T kept in smem (reuses X staging buffer).
#define WSL_XT (256 * 68)
#define WSL_WT (64 * 68)
#define WSL_SMEM ((WSL_XT + 2 * WSL_WT) * 4)   // 104448 bytes

__global__ __launch_bounds__(256, 2)
void wsum_ln(const float* __restrict__ x0, const float* __restrict__ x1,
             const float* __restrict__ x2, const float* __restrict__ x3,
             const float* __restrict__ Wl,       // (4,64,64)
             const float* __restrict__ Sn,       // (64,64)
             const float* __restrict__ bconv_l,  // (4,64)
             const float* __restrict__ gamma_l,  // (64,64)
             const float* __restrict__ beta_l,   // (64,64)
             float* __restrict__ Xout) {
    extern __shared__ float wsm[];
    float (*Xs)[68]  = (float (*)[68])(wsm);                 // reused as T
    float (*Ws)[68]  = (float (*)[68])(wsm + WSL_XT);
    float (*Sns)[68] = (float (*)[68])(wsm + WSL_XT + WSL_WT);
    __shared__ float red[8];
    __shared__ float s_mu, s_rstd;

    const int t = threadIdx.x;
    const long r0 = (long)blockIdx.x * 256;
    const int lane = t & 31;
    const int g  = lane >> 2;        // 0..7
    const int tg = lane & 3;         // 0..3
    const int w  = t >> 5;
    const int wr = w >> 1;           // 0..3 : 64-row group
    const int wc = w & 1;            // 0..1 : 32-col group

    // stage Sn pre-sync (produced many kernels ago — provably complete)
    #pragma unroll
    for (int i = 0; i < 16; i++) {
        int idx = t + i * 256;
        Sns[idx >> 6][idx & 63] = Sn[idx];
    }
    cudaTriggerProgrammaticLaunchCompletion();
    cudaGridDependencySynchronize();

    float c[4][4][4];
    #pragma unroll
    for (int im = 0; im < 4; im++)
        #pragma unroll
        for (int in = 0; in < 4; in++) {
            c[im][in][0] = 0.f; c[im][in][1] = 0.f;
            c[im][in][2] = 0.f; c[im][in][3] = 0.f;
        }

    const float* xs[4] = { x0, x1, x2, x3 };

    #pragma unroll
    for (int s = 0; s < 4; s++) {
        __syncthreads();                 // smem reuse guard
        #pragma unroll
        for (int j = 0; j < 16; j++) {
            int idx = t + 256 * j;
            int row = idx >> 4, c4 = (idx & 15) * 4;
            *(float4*)&Xs[row][c4] =
                *(const float4*)(xs[s] + (r0 + row) * 64 + c4);
        }
        #pragma unroll
        for (int j = 0; j < 4; j++) {
            int idx = t + 256 * j;
            int kr = idx >> 4, c4 = (idx & 15) * 4;
            *(float4*)&Ws[kr][c4] =
                *(const float4*)(Wl + s * 4096 + kr * 64 + c4);
        }
        __syncthreads();

        #pragma unroll
        for (int kc = 0; kc < 8; kc++) {
            const int kr = kc * 8;
            uint32_t ah[4][4], bh[4][2];
            #pragma unroll
            for (int im = 0; im < 4; im++) {
                const int rb = wr * 64 + im * 16 + g;
                ah[im][0] = __float_as_uint(Xs[rb    ][kr + tg]);
                ah[im][1] = __float_as_uint(Xs[rb + 8][kr + tg]);
                ah[im][2] = __float_as_uint(Xs[rb    ][kr + tg + 4]);
                ah[im][3] = __float_as_uint(Xs[rb + 8][kr + tg + 4]);
            }
            #pragma unroll
            for (int in = 0; in < 4; in++) {
                const int cb = wc * 32 + in * 8 + g;
                bh[in][0] = __float_as_uint(Ws[kr + tg    ][cb]);
                bh[in][1] = __float_as_uint(Ws[kr + tg + 4][cb]);
            }
            #pragma unroll
            for (int im = 0; im < 4; im++)
                #pragma unroll
                for (int in = 0; in < 4; in++)
                    mma_tf32(c[im][in], ah[im], bh[in]);
        }
    }

    // write T tile into Xs (staging buffer is dead now)
    __syncthreads();
    #pragma unroll
    for (int im = 0; im < 4; im++) {
        const int row = wr * 64 + im * 16 + g;
        #pragma unroll
        for (int in = 0; in < 4; in++) {
            const int col = wc * 32 + in * 8 + 2 * tg;
            *(float2*)&Xs[row][col]     = make_float2(c[im][in][0], c[im][in][1]);
            *(float2*)&Xs[row + 8][col] = make_float2(c[im][in][2], c[im][in][3]);
        }
    }
    __syncthreads();

    // ---------------- LN phase: 4 n's sequentially, all 256 threads each ----
    const int u = t >> 2;
    const int q = t & 3;
    const int lane2 = t & 31, wid = t >> 5;

    unsigned long long hb[4][2];
    float4 g4[4], b4[4];
    #pragma unroll
    for (int v = 0; v < 4; v++) {
        #pragma unroll
        for (int jj = 0; jj < 2; jj++) {
            int cc = q * 4 + 16 * v + 2 * jj;
            float b0 = bconv_l[cc]       + bconv_l[64 + cc]
                     + bconv_l[128 + cc] + bconv_l[192 + cc];
            float b1 = bconv_l[cc + 1]       + bconv_l[64 + cc + 1]
                     + bconv_l[128 + cc + 1] + bconv_l[192 + cc + 1];
            hb[v][jj] = pack2f(b0, b1);
        }
        g4[v] = *(const float4*)(gamma_l + u * 64 + q * 4 + 16 * v);
        b4[v] = *(const float4*)(beta_l  + u * 64 + q * 4 + 16 * v);
    }

    for (int s4 = 0; s4 < 4; s4++) {
        unsigned long long h2[4][2];
        #pragma unroll
        for (int v = 0; v < 4; v++) { h2[v][0] = hb[v][0]; h2[v][1] = hb[v][1]; }

        #pragma unroll 8
        for (int k = 0; k < 64; k++) {
            unsigned long long sv = pack2(Sns[u][k]);
            #pragma unroll
            for (int v = 0; v < 4; v++) {
                ulonglong2 ww = *(const ulonglong2*)&Xs[s4 * 64 + k][q * 4 + 16 * v];
                fma2(h2[v][0], sv, ww.x);
                fma2(h2[v][1], sv, ww.y);
            }
        }

        float h[16];
        #pragma unroll
        for (int v = 0; v < 4; v++) {
            float2 a0 = unpack2(h2[v][0]);
            float2 a1 = unpack2(h2[v][1]);
            h[4 * v + 0] = a0.x; h[4 * v + 1] = a0.y;
            h[4 * v + 2] = a1.x; h[4 * v + 3] = a1.y;
        }

        float lsum = 0.0f;
        #pragma unroll
        for (int j = 0; j < 16; j++) lsum += h[j];
        #pragma unroll
        for (int o = 16; o > 0; o >>= 1) lsum += __shfl_xor_sync(0xffffffffu, lsum, o);
        if (lane2 == 0) red[wid] = lsum;
        __syncthreads();
        if (t == 0) {
            float s = 0.0f;
            #pragma unroll
            for (int i = 0; i < 8; i++) s += red[i];
            s_mu = s * (1.0f / 4096.0f);
        }
        __syncthreads();
        const float mu = s_mu;

        float lv = 0.0f;
        #pragma unroll
        for (int j = 0; j < 16; j++) { float d = h[j] - mu; lv += d * d; }
        #pragma unroll
        for (int o = 16; o > 0; o >>= 1) lv += __shfl_xor_sync(0xffffffffu, lv, o);
        if (lane2 == 0) red[wid] = lv;
        __syncthreads();
        if (t == 0) {
            float s = 0.0f;
            #pragma unroll
            for (int i = 0; i < 8; i++) s += red[i];
            s_rstd = rsqrtf(s * (1.0f / 4096.0f) + LN_EPS);
        }
        __syncthreads();
        const float rstd = s_rstd;

        float* xo = Xout + ((long)(blockIdx.x * 4 + s4)) * FDIM + u * 64;
        #pragma unroll
        for (int v = 0; v < 4; v++) {
            const int cc = q * 4 + 16 * v;
            float4 o;
            o.x = fmaxf((h[4 * v + 0] - mu) * rstd * g4[v].x + b4[v].x, 0.0f);
            o.y = fmaxf((h[4 * v + 1] - mu) * rstd * g4[v].y + b4[v].y, 0.0f);
            o.z = fmaxf((h[4 * v + 2] - mu) * rstd * g4[v].z + b4[v].z, 0.0f);
            o.w = fmaxf((h[4 * v + 3] - mu) * rstd * g4[v].w + b4[v].w, 0.0f);
            *(float4*)(xo + cc) = o;
        }
    }
}

// ----------- readout: out(2048,64) = X(2048,4096) @ Wl(4096,64) + bl --------
__global__ __launch_bounds__(256)
void final_gemm(const float* __restrict__ X, const float* __restrict__ Wl,
                const float* __restrict__ bl, float* __restrict__ out) {
    __shared__ float Xs[16][128];
    __shared__ float Ws[128][68];
    const int t = threadIdx.x;
    const long m0 = (long)blockIdx.x * 16;
    const int r  = t >> 4;
    const int cq = (t & 15) * 4;

    cudaGridDependencySynchronize();

    float acc[4] = {0.f, 0.f, 0.f, 0.f};

    for (int k0 = 0; k0 < FDIM; k0 += 128) {
        #pragma unroll
        for (int i = 0; i < 2; i++) {
            int idx = t + i * 256;
            int rr = idx >> 5, cc = (idx & 31) * 4;
            *(float4*)&Xs[rr][cc] = *(const float4*)(X + (m0 + rr) * FDIM + k0 + cc);
        }
        #pragma unroll
        for (int i = 0; i < 8; i++) {
            int idx = t + i * 256;
            int kk = idx >> 4, cc = (idx & 15) * 4;
            float4 v = *(const float4*)(Wl + (long)(k0 + kk) * 64 + cc);
            Ws[kk][cc] = v.x; Ws[kk][cc + 1] = v.y; Ws[kk][cc + 2] = v.z; Ws[kk][cc + 3] = v.w;
        }
        __syncthreads();
        #pragma unroll 16
        for (int kk = 0; kk < 128; kk++) {
            float xv = Xs[r][kk];
            #pragma unroll
            for (int j = 0; j < 4; j++) acc[j] += xv * Ws[kk][cq + j];
        }
        __syncthreads();
    }
    float4 v = make_float4(acc[0] + bl[cq], acc[1] + bl[cq + 1],
                           acc[2] + bl[cq + 2], acc[3] + bl[cq + 3]);
    *(float4*)(out + (m0 + r) * 64 + cq) = v;
}

// ---------------------------------------------------------------------------
static inline void launch_gemm_pdl(dim3 grid, const float* A, const float* B,
                                   float* C, int M, int N, int K) {
    cudaLaunchConfig_t cfg = {};
    cfg.gridDim = grid; cfg.blockDim = dim3(256);
    cfg.dynamicSmemBytes = GEMM_SMEM; cfg.stream = 0;
    cudaLaunchAttribute at[1];
    at[0].id = cudaLaunchAttributeProgrammaticStreamSerialization;
    at[0].val.programmaticStreamSerializationAllowed = 1;
    cfg.attrs = at; cfg.numAttrs = 1;
    cudaLaunchKernelEx(&cfg, gemm_tt, A, B, C, M, N, K);
}

extern "C" void kernel_launch(void* const* d_in, const int* in_sizes, int n_in,
                              void* d_out, int out_size) {
    const float* x_in    = (const float*)d_in[0];   // (2048,64,64)
    const int*   sub_adj = (const int*)  d_in[1];   // (64,64)
    const int*   adj     = (const int*)  d_in[2];   // (2048,2048)
    const float* W_convs = (const float*)d_in[3];   // (3,4,64,64)
    const float* b_convs = (const float*)d_in[4];   // (3,4,64)
    const float* ln_g    = (const float*)d_in[5];   // (3,64,64)
    const float* ln_b    = (const float*)d_in[6];   // (3,64,64)
    const float* W_lin   = (const float*)d_in[7];   // (4096,64)
    const float* b_lin   = (const float*)d_in[8];   // (64)
    float* out = (float*)d_out;

    float *Af, *AT, *A2, *A3, *X, *B1, *B2, *B3, *Sn;
    cudaGetSymbolAddress((void**)&Af, g_Af);
    cudaGetSymbolAddress((void**)&AT, g_AT);
    cudaGetSymbolAddress((void**)&A2, g_A2);
    cudaGetSymbolAddress((void**)&A3, g_A3);
    cudaGetSymbolAddress((void**)&X,  g_X);
    cudaGetSymbolAddress((void**)&B1, g_B1);
    cudaGetSymbolAddress((void**)&B2, g_B2);
    cudaGetSymbolAddress((void**)&B3, g_B3);
    cudaGetSymbolAddress((void**)&Sn, g_Sn);

    cudaFuncSetAttribute(gemm_tt, cudaFuncAttributeMaxDynamicSharedMemorySize,
                         GEMM_SMEM);
    cudaFuncSetAttribute(wsum_ln, cudaFuncAttributeMaxDynamicSharedMemorySize,
                         WSL_SMEM);

    // precompute: Af + AfT in one pass; (A^2)^T, (A^3)^T (exact int GEMMs); Sn
    cast_both<<<dim3(NN / 32, NN / 32), dim3(32, 8)>>>(adj, Af, AT);
    // sq1 reads BOTH operands from the immediate predecessor -> plain launch
    gemm_tt<<<dim3(NN / TBN, NN / TBM), 256, GEMM_SMEM>>>(Af, AT, A2, NN, NN, NN);
    // sq2: A-op Af is 2 back -> PDL safe
    launch_gemm_pdl(dim3(NN / TBN, NN / TBM), Af, A2, A3, NN, NN, NN);
    compute_sn<<<1, 256>>>(sub_adj, Sn);

    const dim3 gmeta(FDIM / TBN, NN / TBM);   // (32, 8)
    for (int l = 0; l < 3; l++) {
        const float* curX = (l == 0) ? x_in : X;
        const float* Wl = W_convs + (long)l * 4 * 4096;

        // x1 = A @ x ; x2 = A^2 @ x1 ; x3 = A^3 @ x2  (all PDL: A-op ancient)
        launch_gemm_pdl(gmeta, AT, curX, B1, NN, FDIM, NN);
        launch_gemm_pdl(gmeta, A2, B1,  B2, NN, FDIM, NN);
        launch_gemm_pdl(gmeta, A3, B2,  B3, NN, FDIM, NN);

        // X = relu(LN(Sn @ (sum_i xi Wi) + sum_i b_i))  — fused, PDL
        {
            cudaLaunchConfig_t cfg = {};
            cfg.gridDim = dim3((NN * MDIM) / 256); cfg.blockDim = dim3(256);
            cfg.dynamicSmemBytes = WSL_SMEM; cfg.stream = 0;
            cudaLaunchAttribute at[1];
            at[0].id = cudaLaunchAttributeProgrammaticStreamSerialization;
            at[0].val.programmaticStreamSerializationAllowed = 1;
            cfg.attrs = at; cfg.numAttrs = 1;
            cudaLaunchKernelEx(&cfg, wsum_ln, curX,
                               (const float*)B1, (const float*)B2,
                               (const float*)B3, Wl, (const float*)Sn,
                               b_convs + (long)l * 256,
                               ln_g + (long)l * 4096,
                               ln_b + (long)l * 4096, X);
        }
    }

    // readout (PDL; sync at kernel start before reading X)
    {
        cudaLaunchConfig_t cfg = {};
        cfg.gridDim = dim3(NN / 16); cfg.blockDim = dim3(256);
        cfg.dynamicSmemBytes = 0; cfg.stream = 0;
        cudaLaunchAttribute at[1];
        at[0].id = cudaLaunchAttributeProgrammaticStreamSerialization;
        at[0].val.programmaticStreamSerializationAllowed = 1;
        cfg.attrs = at; cfg.numAttrs = 1;
        cudaLaunchKernelEx(&cfg, final_gemm, (const float*)X, W_lin, b_lin, out);
    }
}

// round 16
// speedup vs baseline: 1.4710x; 1.4710x over previous
#include <cuda_runtime.h>
#include <cuda_fp16.h>
#include <cstdint>

// Problem constants
#define NN    2048
#define MDIM  64
#define DDIM  64
#define FDIM  4096
#define OUTD  64
#define LN_EPS 1e-5f

// scaling (powers of two, exact)
#define SC_B2   (1.0f / 4096.0f)    // B2 packed scale (2^-12)
#define SC_A3   (1.0f / 16.0f)      // A^3 packed scale (2^-4)
#define SC_C3   65536.0f            // prop3 fp32 output rescale (2^16)

// ------------------------- scratch (device globals) -------------------------
__device__ uint32_t g_ApL [NN * NN / 2];   // A  packed [M][K/2] (left style)
__device__ uint32_t g_ApB [NN * NN / 2];   // A  packed [K/2][N] (B style)
__device__ uint32_t g_A2pL[NN * NN / 2];
__device__ uint32_t g_A2pB[NN * NN / 2];
__device__ uint32_t g_A3pL[NN * NN / 2];
__device__ uint32_t g_Xp  [NN * FDIM / 2]; // packed features (B style)
__device__ uint32_t g_B1p [NN * FDIM / 2];
__device__ uint32_t g_B2p [NN * FDIM / 2];
__device__ float g_B1[NN * FDIM];
__device__ float g_B2[NN * FDIM];
__device__ float g_B3[NN * FDIM];
__device__ float g_X [NN * FDIM];
__device__ float g_T [NN * FDIM];
__device__ float g_Sn[MDIM * MDIM];

// ------------------------- small helpers -------------------------------------
__device__ __forceinline__ uint32_t h2s(float lo, float hi) {
    __half2 h = __floats2half2_rn(lo, hi);
    return *(uint32_t*)&h;
}

// adj(int) -> ApL [2048][1024] and ApB [1024][2048]
__global__ void cast_pack(const int* __restrict__ adj,
                          uint32_t* __restrict__ ApL,
                          uint32_t* __restrict__ ApB) {
    int idx = blockIdx.x * 256 + threadIdx.x;     // 0 .. 2M-1
    {   // ApL: word(m, kk) = (A[m][2kk], A[m][2kk+1])
        int m = idx >> 10, kk = idx & 1023;
        int2 v = *(const int2*)(adj + (long)m * NN + (kk << 1));
        ApL[idx] = h2s((float)v.x, (float)v.y);
    }
    {   // ApB: word(kk, n) = (A[2kk][n], A[2kk+1][n])
        int kk = idx >> 11, n = idx & 2047;
        int a = adj[(long)(2 * kk) * NN + n];
        int b = adj[(long)(2 * kk + 1) * NN + n];
        ApB[idx] = h2s((float)a, (float)b);
    }
}

// fp32 [R][C] -> packed fp16 [R/2][C] words (pairs along rows)
__global__ void pack_rows(const float* __restrict__ src,
                          uint32_t* __restrict__ dst, int C) {
    long tid4 = ((long)blockIdx.x * 256 + threadIdx.x) * 4;
    int kk = (int)(tid4 / C), f = (int)(tid4 % C);
    float4 a = *(const float4*)(src + (long)(2 * kk) * C + f);
    float4 b = *(const float4*)(src + (long)(2 * kk + 1) * C + f);
    uint4 o;
    o.x = h2s(a.x, b.x); o.y = h2s(a.y, b.y);
    o.z = h2s(a.z, b.z); o.w = h2s(a.w, b.w);
    *(uint4*)(dst + tid4) = o;
}

// ------------------------- Sn = D^-1/2 (S+I) D^-1/2 --------------------------
__global__ void compute_sn(const int* __restrict__ sub_adj, float* __restrict__ Sn) {
    __shared__ float part[MDIM][4];
    __shared__ float dinv[MDIM];
    const int t = threadIdx.x;
    const int u = t >> 2, q = t & 3;
    float s = 0.0f;
    #pragma unroll
    for (int v = 0; v < 16; v++) s += (float)sub_adj[u * MDIM + q * 16 + v];
    part[u][q] = s;
    __syncthreads();
    if (q == 0)
        dinv[u] = rsqrtf(1.0f + part[u][0] + part[u][1] + part[u][2] + part[u][3]);
    __syncthreads();
    #pragma unroll
    for (int j = 0; j < 16; j++) {
        int idx = t + j * 256;
        int uu = idx >> 6, vv = idx & 63;
        float a = (float)sub_adj[idx] + (uu == vv ? 1.0f : 0.0f);
        Sn[idx] = dinv[uu] * a * dinv[vv];
    }
}

// ------------------------- mma / cp.async / f32x2 ----------------------------
__device__ __forceinline__ void mma_tf32(float c[4], const uint32_t a[4],
                                         const uint32_t b[2]) {
    asm volatile(
        "mma.sync.aligned.m16n8k8.row.col.f32.tf32.tf32.f32 "
        "{%0,%1,%2,%3}, {%4,%5,%6,%7}, {%8,%9}, {%0,%1,%2,%3};\n"
        : "+f"(c[0]), "+f"(c[1]), "+f"(c[2]), "+f"(c[3])
        : "r"(a[0]), "r"(a[1]), "r"(a[2]), "r"(a[3]), "r"(b[0]), "r"(b[1]));
}
__device__ __forceinline__ void mma_f16(float c[4], const uint32_t a[4],
                                        const uint32_t b[2]) {
    asm volatile(
        "mma.sync.aligned.m16n8k16.row.col.f32.f16.f16.f32 "
        "{%0,%1,%2,%3}, {%4,%5,%6,%7}, {%8,%9}, {%0,%1,%2,%3};\n"
        : "+f"(c[0]), "+f"(c[1]), "+f"(c[2]), "+f"(c[3])
        : "r"(a[0]), "r"(a[1]), "r"(a[2]), "r"(a[3]), "r"(b[0]), "r"(b[1]));
}
__device__ __forceinline__ void cp16u(uint32_t* smem, const uint32_t* gmem) {
    uint32_t s = (uint32_t)__cvta_generic_to_shared(smem);
    asm volatile("cp.async.cg.shared.global [%0], [%1], 16;\n" :: "r"(s), "l"(gmem));
}
__device__ __forceinline__ void cp16(float* smem, const float* gmem) {
    uint32_t s = (uint32_t)__cvta_generic_to_shared(smem);
    asm volatile("cp.async.cg.shared.global [%0], [%1], 16;\n" :: "r"(s), "l"(gmem));
}
__device__ __forceinline__ void cp_commit() {
    asm volatile("cp.async.commit_group;\n");
}
template<int W> __device__ __forceinline__ void cp_wait() {
    asm volatile("cp.async.wait_group %0;\n" :: "n"(W));
}
__device__ __forceinline__ unsigned long long pack2(float x) {
    unsigned long long r;
    asm("mov.b64 %0, {%1, %1};" : "=l"(r) : "f"(x));
    return r;
}
__device__ __forceinline__ unsigned long long pack2f(float lo, float hi) {
    unsigned long long r;
    asm("mov.b64 %0, {%1, %2};" : "=l"(r) : "f"(lo), "f"(hi));
    return r;
}
__device__ __forceinline__ void fma2(unsigned long long& d, unsigned long long a,
                                     unsigned long long b) {
    asm("fma.rn.f32x2 %0, %1, %2, %0;" : "+l"(d) : "l"(a), "l"(b));
}
__device__ __forceinline__ float2 unpack2(unsigned long long v) {
    float2 f;
    asm("mov.b64 {%0, %1}, %2;" : "=f"(f.x), "=f"(f.y) : "l"(v));
    return f;
}

// ================= fp16 tensor GEMM: C(MxN) = P(MxK) * B(KxN) ================
// P packed [M][K/2] words (k-pairs); B packed [K/2][N] words (k-pairs).
// CTA 256x128, k-tile 64, 3-stage cp.async, 8 warps (4x2), warp 64x64.
// Outputs (each optional): fp32 C*cscale; P-style pack CpL [M][N/2]*pscale;
// B-style pack CpB [M/2][N]*pscale (via shfl_xor row-pair exchange).
#define HS_AW 36                       // A smem row pitch (words) 32+4 pad
#define HS_BW 132                      // B smem row pitch (words) 128+4 pad
#define HS_AST (256 * HS_AW)           // 9216 words / stage
#define HS_BST (32 * HS_BW)            // 4224 words / stage
#define GEMMH_SMEM (3 * (HS_AST + HS_BST) * 4)   // 161280 bytes

__global__ __launch_bounds__(256, 1)
void gemm_h(const uint32_t* __restrict__ Pp, const uint32_t* __restrict__ Bp,
            float* __restrict__ C, uint32_t* __restrict__ CpL,
            uint32_t* __restrict__ CpB, float cscale, float pscale,
            int M, int N, int K) {
    extern __shared__ uint32_t hsm[];
    uint32_t* As = hsm;
    uint32_t* Bs = hsm + 3 * HS_AST;

    const int t = threadIdx.x;
    const long bm = (long)blockIdx.y * 256;
    const long bn = (long)blockIdx.x * 128;
    const int lane = t & 31;
    const int g  = lane >> 2;            // 0..7
    const int tg = lane & 3;             // 0..3
    const int w  = t >> 5;
    const int wm = (w >> 1) * 64;        // 0,64,128,192
    const int wn = (w & 1) * 64;         // 0 or 64
    const int K2 = K >> 1;

    // staging maps
    const int ar = t >> 3;               // 0..31 (A rows ar+32j)
    const int ac = t & 7;                // A chunk (16B) within row
    const uint32_t* Ag = Pp + (bm + ar) * (long)K2 + ac * 4;
    const int br = t >> 3;               // 0..31 (B kk row)
    const int bc = t & 7;                // B chunk base

    float c[4][8][4];
    #pragma unroll
    for (int im = 0; im < 4; im++)
        #pragma unroll
        for (int in = 0; in < 8; in++) {
            c[im][in][0] = 0.f; c[im][in][1] = 0.f;
            c[im][in][2] = 0.f; c[im][in][3] = 0.f;
        }

    const int ktiles = K >> 6;           // k-tile = 64 halves = 32 words

    #pragma unroll
    for (int s = 0; s < 2; s++) {
        const int kw = s * 32;           // word offset of tile
        #pragma unroll
        for (int j = 0; j < 8; j++)
            cp16u(&As[s * HS_AST + (ar + 32 * j) * HS_AW + ac * 4],
                  Ag + (long)32 * j * K2 + kw);
        #pragma unroll
        for (int j = 0; j < 4; j++)
            cp16u(&Bs[s * HS_BST + br * HS_BW + (bc + 8 * j) * 4],
                  Bp + (long)(kw + br) * N + bn + (bc + 8 * j) * 4);
        cp_commit();
    }

    for (int i = 0; i < ktiles; i++) {
        if (i + 2 < ktiles) cp_wait<1>(); else cp_wait<0>();
        __syncthreads();

        const int nx = i + 2;
        if (nx < ktiles) {
            const int st = nx % 3;
            const int kw = nx * 32;
            #pragma unroll
            for (int j = 0; j < 8; j++)
                cp16u(&As[st * HS_AST + (ar + 32 * j) * HS_AW + ac * 4],
                      Ag + (long)32 * j * K2 + kw);
            #pragma unroll
            for (int j = 0; j < 4; j++)
                cp16u(&Bs[st * HS_BST + br * HS_BW + (bc + 8 * j) * 4],
                      Bp + (long)(kw + br) * N + bn + (bc + 8 * j) * 4);
            cp_commit();
        }

        const int cur = i % 3;
        const uint32_t* Ac = As + cur * HS_AST;
        const uint32_t* Bc = Bs + cur * HS_BST;
        #pragma unroll
        for (int c16 = 0; c16 < 4; c16++) {
            const int kw0 = 8 * c16;
            uint32_t af[4][4], bf[8][2];
            #pragma unroll
            for (int im = 0; im < 4; im++) {
                const int r0 = (wm + im * 16 + g) * HS_AW;
                af[im][0] = Ac[r0 + kw0 + tg];
                af[im][1] = Ac[r0 + 8 * HS_AW + kw0 + tg];
                af[im][2] = Ac[r0 + kw0 + tg + 4];
                af[im][3] = Ac[r0 + 8 * HS_AW + kw0 + tg + 4];
            }
            #pragma unroll
            for (int in = 0; in < 8; in++) {
                const int nb = wn + in * 8 + g;
                bf[in][0] = Bc[(kw0 + tg) * HS_BW + nb];
                bf[in][1] = Bc[(kw0 + tg + 4) * HS_BW + nb];
            }
            #pragma unroll
            for (int im = 0; im < 4; im++)
                #pragma unroll
                for (int in = 0; in < 8; in++)
                    mma_f16(c[im][in], af[im], bf[in]);
        }
    }

    // ----------------------------- epilogue ---------------------------------
    #pragma unroll
    for (int im = 0; im < 4; im++) {
        const long row = bm + wm + im * 16 + g;
        #pragma unroll
        for (int in = 0; in < 8; in++) {
            const long col = bn + wn + in * 8 + 2 * tg;
            const float c0 = c[im][in][0], c1 = c[im][in][1];
            const float c2 = c[im][in][2], c3 = c[im][in][3];
            if (C) {
                float* Cp = C + row * N + col;
                *(float2*)Cp = make_float2(c0 * cscale, c1 * cscale);
                *(float2*)(Cp + 8 * N) = make_float2(c2 * cscale, c3 * cscale);
            }
            if (CpL) {
                const long wc = col >> 1;
                CpL[row * (N >> 1) + wc]       = h2s(c0 * pscale, c1 * pscale);
                CpL[(row + 8) * (N >> 1) + wc] = h2s(c2 * pscale, c3 * pscale);
            }
            if (CpB) {
                float p0 = __shfl_xor_sync(0xffffffffu, c0, 4);
                float p1 = __shfl_xor_sync(0xffffffffu, c1, 4);
                float p2 = __shfl_xor_sync(0xffffffffu, c2, 4);
                float p3 = __shfl_xor_sync(0xffffffffu, c3, 4);
                if ((g & 1) == 0) {
                    const long kk = row >> 1;
                    uint2 v;
                    v.x = h2s(c0 * pscale, p0 * pscale);
                    v.y = h2s(c1 * pscale, p1 * pscale);
                    *(uint2*)&CpB[kk * N + col] = v;
                } else {
                    const long kk = (row + 7) >> 1;
                    uint2 v;
                    v.x = h2s(p2 * pscale, c2 * pscale);
                    v.y = h2s(p3 * pscale, c3 * pscale);
                    *(uint2*)&CpB[kk * N + col] = v;
                }
            }
        }
    }
}

// ============ wsum: T = sum_i Xi @ Wi (tf32 single pass, R13-proven) =========
#define WSU_XT (256 * 68)
#define WSU_WT (64 * 68)
#define WSU_SMEM ((WSU_XT + WSU_WT) * 4)   // 87040 bytes

__global__ __launch_bounds__(256, 2)
void wsum(const float* __restrict__ x0, const float* __restrict__ x1,
          const float* __restrict__ x2, const float* __restrict__ x3,
          const float* __restrict__ Wl, float* __restrict__ T) {
    extern __shared__ float wsm[];
    float (*Xs)[68] = (float (*)[68])(wsm);
    float (*Ws)[68] = (float (*)[68])(wsm + WSU_XT);

    const int t = threadIdx.x;
    const long r0 = (long)blockIdx.x * 256;
    const int lane = t & 31;
    const int g  = lane >> 2;
    const int tg = lane & 3;
    const int w  = t >> 5;
    const int wr = w >> 1;
    const int wc = w & 1;

    float c[4][4][4];
    #pragma unroll
    for (int im = 0; im < 4; im++)
        #pragma unroll
        for (int in = 0; in < 4; in++) {
            c[im][in][0] = 0.f; c[im][in][1] = 0.f;
            c[im][in][2] = 0.f; c[im][in][3] = 0.f;
        }

    const float* xs[4] = { x0, x1, x2, x3 };

    #pragma unroll
    for (int s = 0; s < 4; s++) {
        __syncthreads();
        #pragma unroll
        for (int j = 0; j < 16; j++) {
            int idx = t + 256 * j;
            int row = idx >> 4, c4 = (idx & 15) * 4;
            *(float4*)&Xs[row][c4] = *(const float4*)(xs[s] + (r0 + row) * 64 + c4);
        }
        #pragma unroll
        for (int j = 0; j < 4; j++) {
            int idx = t + 256 * j;
            int kr = idx >> 4, c4 = (idx & 15) * 4;
            *(float4*)&Ws[kr][c4] = *(const float4*)(Wl + s * 4096 + kr * 64 + c4);
        }
        __syncthreads();

        #pragma unroll
        for (int kc = 0; kc < 8; kc++) {
            const int kr = kc * 8;
            uint32_t ah[4][4], bh[4][2];
            #pragma unroll
            for (int im = 0; im < 4; im++) {
                const int rb = wr * 64 + im * 16 + g;
                ah[im][0] = __float_as_uint(Xs[rb    ][kr + tg]);
                ah[im][1] = __float_as_uint(Xs[rb + 8][kr + tg]);
                ah[im][2] = __float_as_uint(Xs[rb    ][kr + tg + 4]);
                ah[im][3] = __float_as_uint(Xs[rb + 8][kr + tg + 4]);
            }
            #pragma unroll
            for (int in = 0; in < 4; in++) {
                const int cb = wc * 32 + in * 8 + g;
                bh[in][0] = __float_as_uint(Ws[kr + tg    ][cb]);
                bh[in][1] = __float_as_uint(Ws[kr + tg + 4][cb]);
            }
            #pragma unroll
            for (int im = 0; im < 4; im++)
                #pragma unroll
                for (int in = 0; in < 4; in++)
                    mma_tf32(c[im][in], ah[im], bh[in]);
        }
    }

    #pragma unroll
    for (int im = 0; im < 4; im++) {
        const long row = r0 + wr * 64 + im * 16 + g;
        #pragma unroll
        for (int in = 0; in < 4; in++) {
            const int col = wc * 32 + in * 8 + 2 * tg;
            *(float2*)(T + row * 64 + col)       = make_float2(c[im][in][0], c[im][in][1]);
            *(float2*)(T + (row + 8) * 64 + col) = make_float2(c[im][in][2], c[im][in][3]);
        }
    }
}

// -------- epilogue: h = Sn @ T[n] + bias_sum ; LN(m,d) ; ReLU -> X -----------
__global__ __launch_bounds__(256)
void layer_epilogue(const float* __restrict__ T, const float* __restrict__ Sn,
                    const float* __restrict__ bconv_l,
                    const float* __restrict__ gamma_l,
                    const float* __restrict__ beta_l,
                    float* __restrict__ Xout) {
    __shared__ float Ts[64][68];
    __shared__ float Sns[64][68];
    __shared__ float red[8];
    __shared__ float s_mu, s_rstd;

    const int n = blockIdx.x;
    const int t = threadIdx.x;
    const int u = t >> 2;
    const int q = t & 3;
    const long base = (long)n * FDIM;

    #pragma unroll
    for (int i = 0; i < 16; i++) {
        int idx = t + i * 256;
        Ts[idx >> 6][idx & 63]  = T[base + idx];
        Sns[idx >> 6][idx & 63] = Sn[idx];
    }
    __syncthreads();

    unsigned long long h2[4][2];
    #pragma unroll
    for (int v = 0; v < 4; v++)
        #pragma unroll
        for (int jj = 0; jj < 2; jj++) {
            int c = q * 4 + 16 * v + 2 * jj;
            float b0 = bconv_l[c]       + bconv_l[64 + c]
                     + bconv_l[128 + c] + bconv_l[192 + c];
            float b1 = bconv_l[c + 1]     + bconv_l[64 + c + 1]
                     + bconv_l[128 + c + 1] + bconv_l[192 + c + 1];
            h2[v][jj] = pack2f(b0, b1);
        }
    #pragma unroll 8
    for (int k = 0; k < 64; k++) {
        unsigned long long sv = pack2(Sns[u][k]);
        #pragma unroll
        for (int v = 0; v < 4; v++) {
            ulonglong2 w = *(const ulonglong2*)&Ts[k][q * 4 + 16 * v];
            fma2(h2[v][0], sv, w.x);
            fma2(h2[v][1], sv, w.y);
        }
    }

    float h[16];
    #pragma unroll
    for (int v = 0; v < 4; v++) {
        float2 a0 = unpack2(h2[v][0]);
        float2 a1 = unpack2(h2[v][1]);
        h[4 * v + 0] = a0.x; h[4 * v + 1] = a0.y;
        h[4 * v + 2] = a1.x; h[4 * v + 3] = a1.y;
    }

    const int lane = t & 31, wid = t >> 5;
    float lsum = 0.0f;
    #pragma unroll
    for (int j = 0; j < 16; j++) lsum += h[j];
    #pragma unroll
    for (int o = 16; o > 0; o >>= 1) lsum += __shfl_xor_sync(0xffffffffu, lsum, o);
    if (lane == 0) red[wid] = lsum;
    __syncthreads();
    if (t == 0) {
        float s = 0.0f;
        #pragma unroll
        for (int i = 0; i < 8; i++) s += red[i];
        s_mu = s * (1.0f / 4096.0f);
    }
    __syncthreads();
    const float mu = s_mu;

    float lv = 0.0f;
    #pragma unroll
    for (int j = 0; j < 16; j++) { float d = h[j] - mu; lv += d * d; }
    #pragma unroll
    for (int o = 16; o > 0; o >>= 1) lv += __shfl_xor_sync(0xffffffffu, lv, o);
    if (lane == 0) red[wid] = lv;
    __syncthreads();
    if (t == 0) {
        float s = 0.0f;
        #pragma unroll
        for (int i = 0; i < 8; i++) s += red[i];
        s_rstd = rsqrtf(s * (1.0f / 4096.0f) + LN_EPS);
    }
    __syncthreads();
    const float rstd = s_rstd;

    #pragma unroll
    for (int v = 0; v < 4; v++) {
        const int c = q * 4 + 16 * v;
        const float4 g4 = *(const float4*)(gamma_l + u * 64 + c);
        const float4 b4 = *(const float4*)(beta_l  + u * 64 + c);
        float4 o;
        o.x = fmaxf((h[4 * v + 0] - mu) * rstd * g4.x + b4.x, 0.0f);
        o.y = fmaxf((h[4 * v + 1] - mu) * rstd * g4.y + b4.y, 0.0f);
        o.z = fmaxf((h[4 * v + 2] - mu) * rstd * g4.z + b4.z, 0.0f);
        o.w = fmaxf((h[4 * v + 3] - mu) * rstd * g4.w + b4.w, 0.0f);
        *(float4*)(Xout + base + u * 64 + c) = o;
    }
}

// ----------- readout: out(2048,64) = X(2048,4096) @ Wl(4096,64) + bl --------
__global__ __launch_bounds__(256)
void final_gemm(const float* __restrict__ X, const float* __restrict__ Wl,
                const float* __restrict__ bl, float* __restrict__ out) {
    __shared__ float Xs[16][128];
    __shared__ float Ws[128][68];
    const int t = threadIdx.x;
    const long m0 = (long)blockIdx.x * 16;
    const int r  = t >> 4;
    const int cq = (t & 15) * 4;

    float acc[4] = {0.f, 0.f, 0.f, 0.f};

    for (int k0 = 0; k0 < FDIM; k0 += 128) {
        #pragma unroll
        for (int i = 0; i < 2; i++) {
            int idx = t + i * 256;
            int rr = idx >> 5, cc = (idx & 31) * 4;
            *(float4*)&Xs[rr][cc] = *(const float4*)(X + (m0 + rr) * FDIM + k0 + cc);
        }
        #pragma unroll
        for (int i = 0; i < 8; i++) {
            int idx = t + i * 256;
            int kk = idx >> 4, cc = (idx & 15) * 4;
            float4 v = *(const float4*)(Wl + (long)(k0 + kk) * 64 + cc);
            Ws[kk][cc] = v.x; Ws[kk][cc + 1] = v.y; Ws[kk][cc + 2] = v.z; Ws[kk][cc + 3] = v.w;
        }
        __syncthreads();
        #pragma unroll 16
        for (int kk = 0; kk < 128; kk++) {
            float xv = Xs[r][kk];
            #pragma unroll
            for (int j = 0; j < 4; j++) acc[j] += xv * Ws[kk][cq + j];
        }
        __syncthreads();
    }
    float4 v = make_float4(acc[0] + bl[cq], acc[1] + bl[cq + 1],
                           acc[2] + bl[cq + 2], acc[3] + bl[cq + 3]);
    *(float4*)(out + (m0 + r) * 64 + cq) = v;
}

// ---------------------------------------------------------------------------
extern "C" void kernel_launch(void* const* d_in, const int* in_sizes, int n_in,
                              void* d_out, int out_size) {
    const float* x_in    = (const float*)d_in[0];
    const int*   sub_adj = (const int*)  d_in[1];
    const int*   adj     = (const int*)  d_in[2];
    const float* W_convs = (const float*)d_in[3];
    const float* b_convs = (const float*)d_in[4];
    const float* ln_g    = (const float*)d_in[5];
    const float* ln_b    = (const float*)d_in[6];
    const float* W_lin   = (const float*)d_in[7];
    const float* b_lin   = (const float*)d_in[8];
    float* out = (float*)d_out;

    uint32_t *ApL, *ApB, *A2pL, *A2pB, *A3pL, *Xp, *B1p, *B2p;
    float *B1, *B2, *B3, *X, *T, *Sn;
    cudaGetSymbolAddress((void**)&ApL,  g_ApL);
    cudaGetSymbolAddress((void**)&ApB,  g_ApB);
    cudaGetSymbolAddress((void**)&A2pL, g_A2pL);
    cudaGetSymbolAddress((void**)&A2pB, g_A2pB);
    cudaGetSymbolAddress((void**)&A3pL, g_A3pL);
    cudaGetSymbolAddress((void**)&Xp,   g_Xp);
    cudaGetSymbolAddress((void**)&B1p,  g_B1p);
    cudaGetSymbolAddress((void**)&B2p,  g_B2p);
    cudaGetSymbolAddress((void**)&B1, g_B1);
    cudaGetSymbolAddress((void**)&B2, g_B2);
    cudaGetSymbolAddress((void**)&B3, g_B3);
    cudaGetSymbolAddress((void**)&X,  g_X);
    cudaGetSymbolAddress((void**)&T,  g_T);
    cudaGetSymbolAddress((void**)&Sn, g_Sn);

    cudaFuncSetAttribute(gemm_h, cudaFuncAttributeMaxDynamicSharedMemorySize,
                         GEMMH_SMEM);
    cudaFuncSetAttribute(wsum, cudaFuncAttributeMaxDynamicSharedMemorySize,
                         WSU_SMEM);

    // ---- precompute: packed A forms; A^2, A^3 (exact in fp16); Sn ----------
    cast_pack<<<(NN * NN / 2) / 256, 256>>>(adj, ApL, ApB);
    compute_sn<<<1, 256>>>(sub_adj, Sn);
    // A^2 = A*A : emit both packed forms (exact integers <= ~1150)
    gemm_h<<<dim3(NN / 128, NN / 256), 256, GEMMH_SMEM>>>(
        ApL, ApB, nullptr, A2pL, A2pB, 1.0f, 1.0f, NN, NN, NN);
    // A^3 = A*A^2 : emit left-packed form scaled 2^-4
    gemm_h<<<dim3(NN / 128, NN / 256), 256, GEMMH_SMEM>>>(
        ApL, A2pB, nullptr, A3pL, nullptr, 1.0f, SC_A3, NN, NN, NN);

    const dim3 gprop(FDIM / 128, NN / 256);     // (32, 8)
    for (int l = 0; l < 3; l++) {
        const float* curX = (l == 0) ? x_in : X;
        const float* Wl = W_convs + (long)l * 4 * 4096;

        // pack current features (B-style pairs along n)
        pack_rows<<<(NN / 2 * FDIM) / 4 / 256, 256>>>(curX, Xp, FDIM);

        // x1 = A x        -> fp32 B1 + packed B1p
        gemm_h<<<gprop, 256, GEMMH_SMEM>>>(ApL, Xp, B1, nullptr, B1p,
                                           1.0f, 1.0f, NN, FDIM, NN);
        // x2 = A^2 x1     -> fp32 B2 + packed B2p (scale 2^-12)
        gemm_h<<<gprop, 256, GEMMH_SMEM>>>(A2pL, B1p, B2, nullptr, B2p,
                                           1.0f, SC_B2, NN, FDIM, NN);
        // x3 = A^3 x2     -> fp32 B3 (rescale 2^16 compensates 2^-4 * 2^-12)
        gemm_h<<<gprop, 256, GEMMH_SMEM>>>(A3pL, B2p, B3, nullptr, nullptr,
                                           SC_C3, 1.0f, NN, FDIM, NN);

        // T = sum_i xi @ Wi (tf32), then LN+ReLU
        wsum<<<(NN * MDIM) / 256, 256, WSU_SMEM>>>(curX, B1, B2, B3, Wl, T);
        layer_epilogue<<<NN, 256>>>(T, Sn,
                                    b_convs + (long)l * 256,
                                    ln_g + (long)l * 4096,
                                    ln_b + (long)l * 4096,
                                    X);
    }

    final_gemm<<<NN / 16, 256>>>(X, W_lin, b_lin, out);
}